// round 14
// baseline (speedup 1.0000x reference)
#include <cuda_runtime.h>
#include <stdint.h>
#include <math.h>

#define BB   64
#define TT   52
#define TDEC 51
#define HD   512
#define EE   512
#define GG   2048
#define VV   32000
#define PRED_ELEMS (BB*TDEC*VV)
#define MAXP (BB*TDEC)
#define NBLK 128
#define WP   516
#define RECUR_SMEM ((16*WP + 64*WP + 64*20)*4)   // 170240 bytes
#define SPLIT_T 20

// ------------------------ device scratch ------------------------
__device__ int   g_sort_ind[BB];
__device__ int   g_declen[BB];
__device__ int   g_nt[TDEC];
__device__ int   g_pbase[TDEC];
__device__ int   g_pcount;
__device__ int   g_caps[BB*TT];
__device__ int   g_pt[MAXP];
__device__ int   g_pb[MAXP];
__device__ int   g_pcap[MAXP];
__device__ float g_h[2*BB*HD];                   // double-buffered by step parity
__device__ float g_c[BB*HD];
__device__ float g_X[(size_t)TDEC*BB*GG];
__device__ float g_Hpk[(size_t)MAXP*HD];
__device__ float g_linWr[(size_t)VV*HD];
__device__ unsigned g_bar_count;
__device__ unsigned g_bar_sense;

// ------------------------ helpers ------------------------
__device__ __forceinline__ float to_tf32(float x) {
    float r; asm("cvt.rna.tf32.f32 %0, %1;" : "=f"(r) : "f"(x)); return r;
}
__device__ __forceinline__ void st4_split(float* dh, float* dl, float4 r) {
    float h;
    h=to_tf32(r.x); dh[0]=h; dl[0]=to_tf32(r.x-h);
    h=to_tf32(r.y); dh[1]=h; dl[1]=to_tf32(r.y-h);
    h=to_tf32(r.z); dh[2]=h; dl[2]=to_tf32(r.z-h);
    h=to_tf32(r.w); dh[3]=h; dl[3]=to_tf32(r.w-h);
}
__device__ __forceinline__ void mma8(float* d, const float* a, const float* b) {
    asm volatile("mma.sync.aligned.m16n8k8.row.col.f32.tf32.tf32.f32 "
        "{%0,%1,%2,%3}, {%4,%5,%6,%7}, {%8,%9}, {%0,%1,%2,%3};"
        : "+f"(d[0]), "+f"(d[1]), "+f"(d[2]), "+f"(d[3])
        : "r"(__float_as_uint(a[0])), "r"(__float_as_uint(a[1])),
          "r"(__float_as_uint(a[2])), "r"(__float_as_uint(a[3])),
          "r"(__float_as_uint(b[0])), "r"(__float_as_uint(b[1])));
}
__device__ __forceinline__ void cpasync16(uint32_t saddr, const float* gptr) {
    asm volatile("cp.async.cg.shared.global [%0], [%1], 16;"
                 :: "r"(saddr), "l"(gptr) : "memory");
}
__device__ __forceinline__ unsigned long long pack2(float a, float b) {
    unsigned long long r;
    asm("mov.b64 %0, {%1, %2};" : "=l"(r) : "f"(a), "f"(b));
    return r;
}
__device__ __forceinline__ unsigned long long fma2(unsigned long long a,
                                                   unsigned long long b,
                                                   unsigned long long c) {
    unsigned long long r;
    asm("fma.rn.f32x2 %0, %1, %2, %3;" : "=l"(r) : "l"(a), "l"(b), "l"(c));
    return r;
}
__device__ __forceinline__ float hsum2(unsigned long long v) {
    float a, b;
    asm("mov.b64 {%0, %1}, %2;" : "=f"(a), "=f"(b) : "l"(v));
    return a + b;
}
__device__ __forceinline__ void gridbar(unsigned gen) {
    __syncthreads();
    if (threadIdx.x == 0) {
        unsigned prev;
        asm volatile("atom.release.gpu.global.add.u32 %0, [%1], 1;"
                     : "=r"(prev) : "l"(&g_bar_count) : "memory");
        if (prev == NBLK - 1u) {
            g_bar_count = 0u;
            asm volatile("st.release.gpu.global.u32 [%0], %1;"
                         :: "l"(&g_bar_sense), "r"(gen) : "memory");
        } else {
            unsigned s;
            do {
                asm volatile("ld.acquire.gpu.global.u32 %0, [%1];"
                             : "=r"(s) : "l"(&g_bar_sense) : "memory");
            } while (s != gen);
        }
    }
    __syncthreads();
}

// ------------------------ kernel 1: sort + gathers + pair maps ------------------------
__global__ void setup_kernel(const float* __restrict__ img,
                             const int*   __restrict__ caps_in,
                             const int*   __restrict__ lens,
                             float* __restrict__ out, int out_elems)
{
    __shared__ int s_len[BB];
    int tid = threadIdx.x;
    if (tid < BB) s_len[tid] = lens[tid];
    __syncthreads();

    if (tid == 0) {
        unsigned long long used = 0ull;
        for (int p = 0; p < BB; ++p) {
            int best = -1, bl = -1000000;
            for (int j = 0; j < BB; ++j)
                if (!((used >> j) & 1ull) && s_len[j] > bl) { bl = s_len[j]; best = j; }
            used |= 1ull << best;
            g_sort_ind[p] = best;
            g_declen[p]   = bl - 1;
        }
        g_bar_count = 0u;
        g_bar_sense = 0u;
    }
    __syncthreads();

    if (tid < TDEC) {
        int cnt = 0;
        for (int p = 0; p < BB; ++p) cnt += (g_declen[p] > tid) ? 1 : 0;
        g_nt[tid] = cnt;
    }

    bool wt = (out_elems >= PRED_ELEMS + BB*TT + 2*BB);
    for (int idx = tid; idx < BB*TT; idx += blockDim.x) {
        int p = idx / TT, j = idx - p*TT;
        int c = caps_in[g_sort_ind[p]*TT + j];
        g_caps[idx] = c;
        if (wt) out[PRED_ELEMS + idx] = (float)c;
    }
    for (int idx = tid; idx < BB*HD; idx += blockDim.x) {
        int p = idx >> 9;
        g_h[idx] = img[g_sort_ind[p]*HD + (idx & (HD-1))];   // buffer 0
    }
    if (wt && tid < BB) {
        out[PRED_ELEMS + BB*TT + tid]      = (float)g_declen[tid];
        out[PRED_ELEMS + BB*TT + BB + tid] = (float)g_sort_ind[tid];
    }
    __syncthreads();
    if (tid == 0) {
        int pb = 0;
        for (int t = 0; t < TDEC; ++t) { g_pbase[t] = pb; pb += g_nt[t]; }
        g_pcount = pb;
    }
    __syncthreads();
    if (tid < TDEC) {
        int n = g_nt[tid], pb = g_pbase[tid];
        for (int b = 0; b < n; ++b) {
            g_pt[pb+b]   = tid;
            g_pb[pb+b]   = b;
            g_pcap[pb+b] = g_caps[b*TT + tid];
        }
    }
}

// ------------------------ kernel 1b: pre-round linW to tf32 ------------------------
__global__ void round_linW(const float* __restrict__ w)
{
    size_t i = (size_t)blockIdx.x * blockDim.x + threadIdx.x;
    const float4* src = (const float4*)w;
    float4 v = src[i];
    v.x = to_tf32(v.x); v.y = to_tf32(v.y); v.z = to_tf32(v.z); v.w = to_tf32(v.w);
    ((float4*)g_linWr)[i] = v;
}

// ------------------------ kernel 2: zero-fill inactive rows ------------------------
__global__ void zerofill_kernel(float* __restrict__ out)
{
    int bid = blockIdx.x;
    int b = bid / TDEC, t = bid - b*TDEC;
    if (t < g_declen[b]) return;
    float4 z = make_float4(0.f,0.f,0.f,0.f);
    float4* dst = (float4*)(out + ((size_t)b*TDEC + t)*VV);
    for (int i = threadIdx.x; i < VV/4; i += blockDim.x) dst[i] = z;
}

// ------------------------ kernel 3: xgate via tf32x3 mma ------------------------
__global__ void __launch_bounds__(256) xgate_mma(const float* __restrict__ embW,
                                                const float* __restrict__ Wih,
                                                const float* __restrict__ bih,
                                                const float* __restrict__ bhh)
{
    int P  = g_pcount;
    int m0 = blockIdx.y * 128;
    if (m0 >= P) return;
    int j0 = blockIdx.x * 128;

    __shared__ float Ah[128][20], Al[128][20], Bh[128][20], Bl[128][20];

    int tid  = threadIdx.x;
    int lane = tid & 31, wid = tid >> 5;
    int wm = wid & 1, wn = wid >> 1;
    int gq = lane >> 2, tig = lane & 3;

    int lrow = tid >> 2;
    int lkq  = (tid & 3) * 4;
    int p0 = m0 + lrow, p1 = m0 + lrow + 64;
    bool va0 = p0 < P, va1 = p1 < P;
    const float* a0p = va0 ? (embW + (size_t)g_pcap[p0]*EE + lkq) : (embW + lkq);
    const float* a1p = va1 ? (embW + (size_t)g_pcap[p1]*EE + lkq) : (embW + lkq);
    const float* b0p = Wih + (size_t)(j0+lrow)*EE + lkq;
    const float* b1p = Wih + (size_t)(j0+lrow+64)*EE + lkq;

    float acc[4][4][4];
#pragma unroll
    for (int i=0;i<4;i++)
#pragma unroll
        for (int j=0;j<4;j++)
#pragma unroll
            for (int q=0;q<4;q++) acc[i][j][q] = 0.f;

    for (int kc = 0; kc < 32; ++kc) {
        int k0 = kc*16;
        float4 ra0 = va0 ? *(const float4*)(a0p + k0) : make_float4(0,0,0,0);
        float4 ra1 = va1 ? *(const float4*)(a1p + k0) : make_float4(0,0,0,0);
        float4 rb0 = *(const float4*)(b0p + k0);
        float4 rb1 = *(const float4*)(b1p + k0);
        __syncthreads();
        st4_split(&Ah[lrow][lkq],    &Al[lrow][lkq],    ra0);
        st4_split(&Ah[lrow+64][lkq], &Al[lrow+64][lkq], ra1);
        st4_split(&Bh[lrow][lkq],    &Bl[lrow][lkq],    rb0);
        st4_split(&Bh[lrow+64][lkq], &Bl[lrow+64][lkq], rb1);
        __syncthreads();
#pragma unroll
        for (int k8 = 0; k8 < 2; ++k8) {
            int kb = k8*8;
            float ah[4][4], al[4][4], bh[4][2], bl[4][2];
#pragma unroll
            for (int mt=0;mt<4;mt++) {
                int rm = wm*64 + mt*16;
                ah[mt][0]=Ah[rm+gq][kb+tig];   ah[mt][1]=Ah[rm+gq+8][kb+tig];
                ah[mt][2]=Ah[rm+gq][kb+tig+4]; ah[mt][3]=Ah[rm+gq+8][kb+tig+4];
                al[mt][0]=Al[rm+gq][kb+tig];   al[mt][1]=Al[rm+gq+8][kb+tig];
                al[mt][2]=Al[rm+gq][kb+tig+4]; al[mt][3]=Al[rm+gq+8][kb+tig+4];
            }
#pragma unroll
            for (int nt=0;nt<4;nt++) {
                int rn = wn*32 + nt*8;
                bh[nt][0]=Bh[rn+gq][kb+tig]; bh[nt][1]=Bh[rn+gq][kb+tig+4];
                bl[nt][0]=Bl[rn+gq][kb+tig]; bl[nt][1]=Bl[rn+gq][kb+tig+4];
            }
#pragma unroll
            for (int mt=0;mt<4;mt++)
#pragma unroll
                for (int nt=0;nt<4;nt++) {
                    mma8(acc[mt][nt], ah[mt], bh[nt]);
                    mma8(acc[mt][nt], ah[mt], bl[nt]);
                    mma8(acc[mt][nt], al[mt], bh[nt]);
                }
        }
    }

    float2 lb[4];
#pragma unroll
    for (int nt=0;nt<4;nt++) {
        int v = j0 + wn*32 + nt*8 + tig*2;
        float2 bi = *(const float2*)(bih + v);
        float2 bh2 = *(const float2*)(bhh + v);
        lb[nt].x = bi.x + bh2.x; lb[nt].y = bi.y + bh2.y;
    }
#pragma unroll
    for (int mt=0;mt<4;mt++) {
#pragma unroll
        for (int half=0; half<2; ++half) {
            int ml = wm*64 + mt*16 + gq + half*8;
            int p = m0 + ml;
            if (p < P) {
                int tt = g_pt[p], bb = g_pb[p];
                size_t base = (size_t)tt*BB*GG + (size_t)bb*GG + j0 + wn*32 + tig*2;
#pragma unroll
                for (int nt=0;nt<4;nt++) {
                    float2 val;
                    val.x = acc[mt][nt][half*2+0] + lb[nt].x;
                    val.y = acc[mt][nt][half*2+1] + lb[nt].y;
                    *(float2*)(g_X + base + nt*8) = val;
                }
            }
        }
    }
}

// ------------------------ kernel 4: persistent LSTM recurrence (double-buffered h) ------------------------
__global__ void __launch_bounds__(256) recur_kernel(const float* __restrict__ Whh,
                                                    int t_lo, int t_hi)
{
    extern __shared__ float sm[];
    float* sWT = sm;
    float* sH  = sm + 16*WP;
    float* sG  = sm + 80*WP;

    int tid = threadIdx.x;
    int blk = blockIdx.x;

    for (int idx = tid; idx < 16*HD; idx += 256) {
        int gi = idx >> 9, k = idx & (HD-1);
        int g = gi >> 2, ci = gi & 3;
        sWT[gi*WP + k] = Whh[(size_t)(g*512 + blk*4 + ci)*HD + k];
    }

    int rgrp = tid >> 4;
    int cc   = tid & 15;
    int r0   = rgrp*4;
    int b_u  = tid >> 2;
    int kl   = tid & 3;
    int k_u  = blk*4 + kl;

    const float* wbase = sWT + cc*WP;
    const float* h0p = sH + (size_t)(r0+0)*WP;
    const float* h1p = sH + (size_t)(r0+1)*WP;
    const float* h2p = sH + (size_t)(r0+2)*WP;
    const float* h3p = sH + (size_t)(r0+3)*WP;

    int srow0 = tid >> 7;
    int skq   = tid & 127;
    uint32_t sdst0 = (uint32_t)__cvta_generic_to_shared(sH + (size_t)srow0*WP + skq*4);
    const uint32_t SROWB = 2u*WP*4u;

    float creg = (t_lo == 0) ? 0.f : g_c[(size_t)b_u*HD + k_u];
    __syncthreads();

    for (int t = t_lo; t < t_hi; ++t) {
        int n = g_nt[t];

        const float* gx = g_X + (size_t)t*BB*GG + (size_t)b_u*GG;
        float x0=0.f, x1=0.f, x2=0.f, x3=0.f;
        if (b_u < n) {
            x0 = __ldcg(gx + k_u);
            x1 = __ldcg(gx + 512 + k_u);
            x2 = __ldcg(gx + 1024 + k_u);
            x3 = __ldcg(gx + 1536 + k_u);
        }

        // stage h_t from read buffer (t&1); update writes (t+1)&1 — no WAR race
        const float* sg0 = g_h + (size_t)(t & 1)*BB*HD + (size_t)srow0*HD + skq*4;
        for (int j = 0; srow0 + 2*j < n; ++j) {
            cpasync16(sdst0 + (uint32_t)j*SROWB, sg0 + (size_t)j*2*HD);
        }
        asm volatile("cp.async.commit_group;" ::: "memory");
        asm volatile("cp.async.wait_group 0;" ::: "memory");
        __syncthreads();

        if (r0 < n) {
            unsigned long long a00=0ull,a01=0ull,a10=0ull,a11=0ull,
                               a20=0ull,a21=0ull,a30=0ull,a31=0ull;
#pragma unroll 4
            for (int kq = 0; kq < HD/4; ++kq) {
                float4 wv = *(const float4*)(wbase + 4*kq);
                unsigned long long wxy = pack2(wv.x, wv.y);
                unsigned long long wzw = pack2(wv.z, wv.w);
                float4 v0 = *(const float4*)(h0p + 4*kq);
                float4 v1 = *(const float4*)(h1p + 4*kq);
                float4 v2 = *(const float4*)(h2p + 4*kq);
                float4 v3 = *(const float4*)(h3p + 4*kq);
                a00 = fma2(pack2(v0.x,v0.y), wxy, a00);
                a01 = fma2(pack2(v0.z,v0.w), wzw, a01);
                a10 = fma2(pack2(v1.x,v1.y), wxy, a10);
                a11 = fma2(pack2(v1.z,v1.w), wzw, a11);
                a20 = fma2(pack2(v2.x,v2.y), wxy, a20);
                a21 = fma2(pack2(v2.z,v2.w), wzw, a21);
                a30 = fma2(pack2(v3.x,v3.y), wxy, a30);
                a31 = fma2(pack2(v3.z,v3.w), wzw, a31);
            }
            sG[(r0+0)*20 + cc] = hsum2(a00) + hsum2(a01);
            sG[(r0+1)*20 + cc] = hsum2(a10) + hsum2(a11);
            sG[(r0+2)*20 + cc] = hsum2(a20) + hsum2(a21);
            sG[(r0+3)*20 + cc] = hsum2(a30) + hsum2(a31);
        }
        __syncthreads();

        if (b_u < n) {
            float zi = sG[b_u*20 +  0 + kl] + x0;
            float zf = sG[b_u*20 +  4 + kl] + x1;
            float zg = sG[b_u*20 +  8 + kl] + x2;
            float zo = sG[b_u*20 + 12 + kl] + x3;
            float ii = 1.f/(1.f+expf(-zi));
            float ff = 1.f/(1.f+expf(-zf));
            float gv = tanhf(zg);
            float oo = 1.f/(1.f+expf(-zo));
            creg = ff*creg + ii*gv;
            float hn = oo * tanhf(creg);
            g_h[(size_t)((t+1) & 1)*BB*HD + (size_t)b_u*HD + k_u] = hn;
            g_Hpk[(size_t)(g_pbase[t] + b_u)*HD + k_u] = to_tf32(hn);
        } else if (b_u < BB) {
            // keep write buffer consistent for inactive rows (h carries forward)
            g_h[(size_t)((t+1) & 1)*BB*HD + (size_t)b_u*HD + k_u] =
                g_h[(size_t)(t & 1)*BB*HD + (size_t)b_u*HD + k_u];
        }
        gridbar((unsigned)(t+1));
    }

    g_c[(size_t)b_u*HD + k_u] = creg;
}

// ------------------------ kernel 5: classifier, cp.async double-buffered tf32 mma ------------------------
__global__ void __launch_bounds__(256,2) classifier_mma(int part,
                                                        const float* __restrict__ linb,
                                                        float* __restrict__ out)
{
    int P  = g_pcount;
    int P1 = g_pbase[SPLIT_T];
    int lo = part ? P1 : 0;
    int hi = part ? P  : P1;
    int m0 = blockIdx.y * 128;
    if (m0 >= hi || m0 + 128 <= lo) return;
    int v0 = blockIdx.x * 128;

    __shared__ float As[2][128][20];
    __shared__ float Bs[2][128][20];

    int tid  = threadIdx.x;
    int lane = tid & 31, wid = tid >> 5;
    int wm = wid & 1, wn = wid >> 1;
    int gq = lane >> 2, tig = lane & 3;

    int lrow = tid >> 2;
    int lkq  = (tid & 3) * 4;
    int p0 = m0 + lrow, p1 = m0 + lrow + 64;
    const float* a0p = g_Hpk + (size_t)(p0 < P ? p0 : 0)*HD + lkq;
    const float* a1p = g_Hpk + (size_t)(p1 < P ? p1 : 0)*HD + lkq;
    const float* b0p = g_linWr + (size_t)(v0+lrow)*HD + lkq;
    const float* b1p = g_linWr + (size_t)(v0+lrow+64)*HD + lkq;

    uint32_t sa0 = (uint32_t)__cvta_generic_to_shared(&As[0][lrow][lkq]);
    uint32_t sa1 = (uint32_t)__cvta_generic_to_shared(&As[0][lrow+64][lkq]);
    uint32_t sb0 = (uint32_t)__cvta_generic_to_shared(&Bs[0][lrow][lkq]);
    uint32_t sb1 = (uint32_t)__cvta_generic_to_shared(&Bs[0][lrow+64][lkq]);
    const uint32_t STG = 128*20*4;

    float acc[4][4][4];
#pragma unroll
    for (int i=0;i<4;i++)
#pragma unroll
        for (int j=0;j<4;j++)
#pragma unroll
            for (int q=0;q<4;q++) acc[i][j][q] = 0.f;

    cpasync16(sa0, a0p);
    cpasync16(sa1, a1p);
    cpasync16(sb0, b0p);
    cpasync16(sb1, b1p);
    asm volatile("cp.async.commit_group;" ::: "memory");

    for (int kc = 0; kc < 32; ++kc) {
        if (kc < 31) {
            uint32_t off = ((kc+1)&1) * STG;
            int kn = (kc+1)*16;
            cpasync16(sa0 + off, a0p + kn);
            cpasync16(sa1 + off, a1p + kn);
            cpasync16(sb0 + off, b0p + kn);
            cpasync16(sb1 + off, b1p + kn);
            asm volatile("cp.async.commit_group;" ::: "memory");
            asm volatile("cp.async.wait_group 1;" ::: "memory");
        } else {
            asm volatile("cp.async.wait_group 0;" ::: "memory");
        }
        __syncthreads();

        int buf = kc & 1;
#pragma unroll
        for (int k8 = 0; k8 < 2; ++k8) {
            int kb = k8*8;
            float af[4][4], bf[4][2];
#pragma unroll
            for (int mt=0;mt<4;mt++) {
                int rm = wm*64 + mt*16;
                af[mt][0]=As[buf][rm+gq][kb+tig];   af[mt][1]=As[buf][rm+gq+8][kb+tig];
                af[mt][2]=As[buf][rm+gq][kb+tig+4]; af[mt][3]=As[buf][rm+gq+8][kb+tig+4];
            }
#pragma unroll
            for (int nt=0;nt<4;nt++) {
                int rn = wn*32 + nt*8;
                bf[nt][0]=Bs[buf][rn+gq][kb+tig]; bf[nt][1]=Bs[buf][rn+gq][kb+tig+4];
            }
#pragma unroll
            for (int mt=0;mt<4;mt++)
#pragma unroll
                for (int nt=0;nt<4;nt++)
                    mma8(acc[mt][nt], af[mt], bf[nt]);
        }
        __syncthreads();
    }

    float2 lb[4];
#pragma unroll
    for (int nt=0;nt<4;nt++) {
        int v = v0 + wn*32 + nt*8 + tig*2;
        lb[nt] = *(const float2*)(linb + v);
    }
#pragma unroll
    for (int mt=0;mt<4;mt++) {
#pragma unroll
        for (int half=0; half<2; ++half) {
            int ml = wm*64 + mt*16 + gq + half*8;
            int p = m0 + ml;
            if (p >= lo && p < hi) {
                int tt = g_pt[p], bb = g_pb[p];
                size_t base = ((size_t)bb*TDEC + tt)*VV + v0 + wn*32 + tig*2;
#pragma unroll
                for (int nt=0;nt<4;nt++) {
                    float2 val;
                    val.x = acc[mt][nt][half*2+0] + lb[nt].x;
                    val.y = acc[mt][nt][half*2+1] + lb[nt].y;
                    *(float2*)(out + base + nt*8) = val;
                }
            }
        }
    }
}

// ------------------------ launch ------------------------
extern "C" void kernel_launch(void* const* d_in, const int* in_sizes, int n_in,
                              void* d_out, int out_size)
{
    const float* img  = (const float*)d_in[0];
    const int*   caps = (const int*)  d_in[1];
    const int*   lens = (const int*)  d_in[2];
    const float* embW = (const float*)d_in[3];
    const float* Wih  = (const float*)d_in[4];
    const float* Whh  = (const float*)d_in[5];
    const float* bih  = (const float*)d_in[6];
    const float* bhh  = (const float*)d_in[7];
    const float* linW = (const float*)d_in[8];
    const float* linb = (const float*)d_in[9];
    float* out = (float*)d_out;

    static cudaStream_t s2;
    static cudaEvent_t evA, evR1, evC1;
    static int inited = 0;
    if (!inited) {
        cudaFuncSetAttribute(recur_kernel,
                             cudaFuncAttributeMaxDynamicSharedMemorySize, RECUR_SMEM);
        cudaStreamCreateWithFlags(&s2, cudaStreamNonBlocking);
        cudaEventCreateWithFlags(&evA, cudaEventDisableTiming);
        cudaEventCreateWithFlags(&evR1, cudaEventDisableTiming);
        cudaEventCreateWithFlags(&evC1, cudaEventDisableTiming);
        inited = 1;
    }

    setup_kernel<<<1, 256>>>(img, caps, lens, out, out_size);

    // fork: round_linW + zerofill on s2, concurrent with xgate + recur part 1
    cudaEventRecord(evA, 0);
    cudaStreamWaitEvent(s2, evA, 0);
    round_linW<<<(VV*HD/4)/256, 256, 0, s2>>>(linW);
    zerofill_kernel<<<BB*TDEC, 256, 0, s2>>>(out);

    xgate_mma<<<dim3(GG/128, (MAXP+127)/128), 256>>>(embW, Wih, bih, bhh);
    recur_kernel<<<NBLK, 256, RECUR_SMEM>>>(Whh, 0, SPLIT_T);
    cudaEventRecord(evR1, 0);

    // classifier part 0 (rows for t < SPLIT_T) on s2, concurrent with recur part 2
    cudaStreamWaitEvent(s2, evR1, 0);
    classifier_mma<<<dim3(VV/128, (MAXP+127)/128), 256, 0, s2>>>(0, linb, out);
    cudaEventRecord(evC1, s2);

    recur_kernel<<<NBLK, 256, RECUR_SMEM>>>(Whh, SPLIT_T, TDEC);

    // join + classifier part 1
    cudaStreamWaitEvent(0, evC1, 0);
    classifier_mma<<<dim3(VV/128, (MAXP+127)/128), 256>>>(1, linb, out);
}

// round 17
// speedup vs baseline: 1.1086x; 1.1086x over previous
#include <cuda_runtime.h>
#include <stdint.h>
#include <math.h>

#define BB   64
#define TT   52
#define TDEC 51
#define HD   512
#define EE   512
#define GG   2048
#define VV   32000
#define PRED_ELEMS (BB*TDEC*VV)
#define MAXP (BB*TDEC)
#define NBLK 128
#define WP   516
#define RECUR_SMEM ((16*WP + 64*WP + 64*20)*4)   // 170240 bytes

// ------------------------ device scratch ------------------------
__device__ int   g_sort_ind[BB];
__device__ int   g_declen[BB];
__device__ int   g_nt[TDEC];
__device__ int   g_pbase[TDEC];
__device__ int   g_pcount;
__device__ int   g_caps[BB*TT];
__device__ int   g_pt[MAXP];
__device__ int   g_pb[MAXP];
__device__ int   g_pcap[MAXP];
__device__ float g_h[2*BB*HD];                   // double-buffered by step parity
__device__ float g_X[(size_t)TDEC*BB*GG];
__device__ float g_Hpk[(size_t)MAXP*HD];
__device__ float g_linWr[(size_t)VV*HD];
__device__ unsigned g_bar_count;
__device__ unsigned g_bar_sense;

// ------------------------ helpers ------------------------
__device__ __forceinline__ float to_tf32(float x) {
    float r; asm("cvt.rna.tf32.f32 %0, %1;" : "=f"(r) : "f"(x)); return r;
}
__device__ __forceinline__ void st4_split(float* dh, float* dl, float4 r) {
    float h;
    h=to_tf32(r.x); dh[0]=h; dl[0]=to_tf32(r.x-h);
    h=to_tf32(r.y); dh[1]=h; dl[1]=to_tf32(r.y-h);
    h=to_tf32(r.z); dh[2]=h; dl[2]=to_tf32(r.z-h);
    h=to_tf32(r.w); dh[3]=h; dl[3]=to_tf32(r.w-h);
}
__device__ __forceinline__ void mma8(float* d, const float* a, const float* b) {
    asm volatile("mma.sync.aligned.m16n8k8.row.col.f32.tf32.tf32.f32 "
        "{%0,%1,%2,%3}, {%4,%5,%6,%7}, {%8,%9}, {%0,%1,%2,%3};"
        : "+f"(d[0]), "+f"(d[1]), "+f"(d[2]), "+f"(d[3])
        : "r"(__float_as_uint(a[0])), "r"(__float_as_uint(a[1])),
          "r"(__float_as_uint(a[2])), "r"(__float_as_uint(a[3])),
          "r"(__float_as_uint(b[0])), "r"(__float_as_uint(b[1])));
}
__device__ __forceinline__ void cpasync16(uint32_t saddr, const float* gptr) {
    asm volatile("cp.async.cg.shared.global [%0], [%1], 16;"
                 :: "r"(saddr), "l"(gptr) : "memory");
}
__device__ __forceinline__ unsigned long long pack2(float a, float b) {
    unsigned long long r;
    asm("mov.b64 %0, {%1, %2};" : "=l"(r) : "f"(a), "f"(b));
    return r;
}
__device__ __forceinline__ unsigned long long fma2(unsigned long long a,
                                                   unsigned long long b,
                                                   unsigned long long c) {
    unsigned long long r;
    asm("fma.rn.f32x2 %0, %1, %2, %3;" : "=l"(r) : "l"(a), "l"(b), "l"(c));
    return r;
}
__device__ __forceinline__ float hsum2(unsigned long long v) {
    float a, b;
    asm("mov.b64 {%0, %1}, %2;" : "=f"(a), "=f"(b) : "l"(v));
    return a + b;
}
__device__ __forceinline__ void gridbar(unsigned gen) {
    __syncthreads();
    if (threadIdx.x == 0) {
        unsigned prev;
        asm volatile("atom.release.gpu.global.add.u32 %0, [%1], 1;"
                     : "=r"(prev) : "l"(&g_bar_count) : "memory");
        if (prev == NBLK - 1u) {
            g_bar_count = 0u;
            asm volatile("st.release.gpu.global.u32 [%0], %1;"
                         :: "l"(&g_bar_sense), "r"(gen) : "memory");
        } else {
            unsigned s;
            do {
                asm volatile("ld.acquire.gpu.global.u32 %0, [%1];"
                             : "=r"(s) : "l"(&g_bar_sense) : "memory");
            } while (s < gen);
        }
    }
    __syncthreads();
}

// ------------------------ kernel 1: sort + gathers + pair maps ------------------------
__global__ void setup_kernel(const float* __restrict__ img,
                             const int*   __restrict__ caps_in,
                             const int*   __restrict__ lens,
                             float* __restrict__ out, int out_elems)
{
    __shared__ int s_len[BB];
    int tid = threadIdx.x;
    if (tid < BB) s_len[tid] = lens[tid];
    __syncthreads();

    if (tid == 0) {
        unsigned long long used = 0ull;
        for (int p = 0; p < BB; ++p) {
            int best = -1, bl = -1000000;
            for (int j = 0; j < BB; ++j)
                if (!((used >> j) & 1ull) && s_len[j] > bl) { bl = s_len[j]; best = j; }
            used |= 1ull << best;
            g_sort_ind[p] = best;
            g_declen[p]   = bl - 1;
        }
        g_bar_count = 0u;
        g_bar_sense = 0u;
    }
    __syncthreads();

    if (tid < TDEC) {
        int cnt = 0;
        for (int p = 0; p < BB; ++p) cnt += (g_declen[p] > tid) ? 1 : 0;
        g_nt[tid] = cnt;
    }

    bool wt = (out_elems >= PRED_ELEMS + BB*TT + 2*BB);
    for (int idx = tid; idx < BB*TT; idx += blockDim.x) {
        int p = idx / TT, j = idx - p*TT;
        int c = caps_in[g_sort_ind[p]*TT + j];
        g_caps[idx] = c;
        if (wt) out[PRED_ELEMS + idx] = (float)c;
    }
    for (int idx = tid; idx < BB*HD; idx += blockDim.x) {
        int p = idx >> 9;
        g_h[idx] = img[g_sort_ind[p]*HD + (idx & (HD-1))];   // buffer 0
    }
    if (wt && tid < BB) {
        out[PRED_ELEMS + BB*TT + tid]      = (float)g_declen[tid];
        out[PRED_ELEMS + BB*TT + BB + tid] = (float)g_sort_ind[tid];
    }
    __syncthreads();
    if (tid == 0) {
        int pb = 0;
        for (int t = 0; t < TDEC; ++t) { g_pbase[t] = pb; pb += g_nt[t]; }
        g_pcount = pb;
    }
    __syncthreads();
    if (tid < TDEC) {
        int n = g_nt[tid], pb = g_pbase[tid];
        for (int b = 0; b < n; ++b) {
            g_pt[pb+b]   = tid;
            g_pb[pb+b]   = b;
            g_pcap[pb+b] = g_caps[b*TT + tid];
        }
    }
}

// ------------------------ kernel 1b: pre-round linW to tf32 ------------------------
__global__ void round_linW(const float* __restrict__ w)
{
    size_t i = (size_t)blockIdx.x * blockDim.x + threadIdx.x;
    const float4* src = (const float4*)w;
    float4 v = src[i];
    v.x = to_tf32(v.x); v.y = to_tf32(v.y); v.z = to_tf32(v.z); v.w = to_tf32(v.w);
    ((float4*)g_linWr)[i] = v;
}

// ------------------------ kernel 2: zero-fill inactive rows ------------------------
__global__ void zerofill_kernel(float* __restrict__ out)
{
    int bid = blockIdx.x;
    int b = bid / TDEC, t = bid - b*TDEC;
    if (t < g_declen[b]) return;
    float4 z = make_float4(0.f,0.f,0.f,0.f);
    float4* dst = (float4*)(out + ((size_t)b*TDEC + t)*VV);
    for (int i = threadIdx.x; i < VV/4; i += blockDim.x) dst[i] = z;
}

// ------------------------ kernel 3: xgate via tf32x3 mma ------------------------
__global__ void __launch_bounds__(256) xgate_mma(const float* __restrict__ embW,
                                                const float* __restrict__ Wih,
                                                const float* __restrict__ bih,
                                                const float* __restrict__ bhh)
{
    int P  = g_pcount;
    int m0 = blockIdx.y * 128;
    if (m0 >= P) return;
    int j0 = blockIdx.x * 128;

    __shared__ float Ah[128][20], Al[128][20], Bh[128][20], Bl[128][20];

    int tid  = threadIdx.x;
    int lane = tid & 31, wid = tid >> 5;
    int wm = wid & 1, wn = wid >> 1;
    int gq = lane >> 2, tig = lane & 3;

    int lrow = tid >> 2;
    int lkq  = (tid & 3) * 4;
    int p0 = m0 + lrow, p1 = m0 + lrow + 64;
    bool va0 = p0 < P, va1 = p1 < P;
    const float* a0p = va0 ? (embW + (size_t)g_pcap[p0]*EE + lkq) : (embW + lkq);
    const float* a1p = va1 ? (embW + (size_t)g_pcap[p1]*EE + lkq) : (embW + lkq);
    const float* b0p = Wih + (size_t)(j0+lrow)*EE + lkq;
    const float* b1p = Wih + (size_t)(j0+lrow+64)*EE + lkq;

    float acc[4][4][4];
#pragma unroll
    for (int i=0;i<4;i++)
#pragma unroll
        for (int j=0;j<4;j++)
#pragma unroll
            for (int q=0;q<4;q++) acc[i][j][q] = 0.f;

    for (int kc = 0; kc < 32; ++kc) {
        int k0 = kc*16;
        float4 ra0 = va0 ? *(const float4*)(a0p + k0) : make_float4(0,0,0,0);
        float4 ra1 = va1 ? *(const float4*)(a1p + k0) : make_float4(0,0,0,0);
        float4 rb0 = *(const float4*)(b0p + k0);
        float4 rb1 = *(const float4*)(b1p + k0);
        __syncthreads();
        st4_split(&Ah[lrow][lkq],    &Al[lrow][lkq],    ra0);
        st4_split(&Ah[lrow+64][lkq], &Al[lrow+64][lkq], ra1);
        st4_split(&Bh[lrow][lkq],    &Bl[lrow][lkq],    rb0);
        st4_split(&Bh[lrow+64][lkq], &Bl[lrow+64][lkq], rb1);
        __syncthreads();
#pragma unroll
        for (int k8 = 0; k8 < 2; ++k8) {
            int kb = k8*8;
            float ah[4][4], al[4][4], bh[4][2], bl[4][2];
#pragma unroll
            for (int mt=0;mt<4;mt++) {
                int rm = wm*64 + mt*16;
                ah[mt][0]=Ah[rm+gq][kb+tig];   ah[mt][1]=Ah[rm+gq+8][kb+tig];
                ah[mt][2]=Ah[rm+gq][kb+tig+4]; ah[mt][3]=Ah[rm+gq+8][kb+tig+4];
                al[mt][0]=Al[rm+gq][kb+tig];   al[mt][1]=Al[rm+gq+8][kb+tig];
                al[mt][2]=Al[rm+gq][kb+tig+4]; al[mt][3]=Al[rm+gq+8][kb+tig+4];
            }
#pragma unroll
            for (int nt=0;nt<4;nt++) {
                int rn = wn*32 + nt*8;
                bh[nt][0]=Bh[rn+gq][kb+tig]; bh[nt][1]=Bh[rn+gq][kb+tig+4];
                bl[nt][0]=Bl[rn+gq][kb+tig]; bl[nt][1]=Bl[rn+gq][kb+tig+4];
            }
#pragma unroll
            for (int mt=0;mt<4;mt++)
#pragma unroll
                for (int nt=0;nt<4;nt++) {
                    mma8(acc[mt][nt], ah[mt], bh[nt]);
                    mma8(acc[mt][nt], ah[mt], bl[nt]);
                    mma8(acc[mt][nt], al[mt], bh[nt]);
                }
        }
    }

    float2 lb[4];
#pragma unroll
    for (int nt=0;nt<4;nt++) {
        int v = j0 + wn*32 + nt*8 + tig*2;
        float2 bi = *(const float2*)(bih + v);
        float2 bh2 = *(const float2*)(bhh + v);
        lb[nt].x = bi.x + bh2.x; lb[nt].y = bi.y + bh2.y;
    }
#pragma unroll
    for (int mt=0;mt<4;mt++) {
#pragma unroll
        for (int half=0; half<2; ++half) {
            int ml = wm*64 + mt*16 + gq + half*8;
            int p = m0 + ml;
            if (p < P) {
                int tt = g_pt[p], bb = g_pb[p];
                size_t base = (size_t)tt*BB*GG + (size_t)bb*GG + j0 + wn*32 + tig*2;
#pragma unroll
                for (int nt=0;nt<4;nt++) {
                    float2 val;
                    val.x = acc[mt][nt][half*2+0] + lb[nt].x;
                    val.y = acc[mt][nt][half*2+1] + lb[nt].y;
                    *(float2*)(g_X + base + nt*8) = val;
                }
            }
        }
    }
}

// ------------------------ kernel 4: persistent LSTM recurrence (double-buffered h) ------------------------
__global__ void __launch_bounds__(256) recur_kernel(const float* __restrict__ Whh)
{
    extern __shared__ float sm[];
    float* sWT = sm;
    float* sH  = sm + 16*WP;
    float* sG  = sm + 80*WP;

    int tid = threadIdx.x;
    int blk = blockIdx.x;

    for (int idx = tid; idx < 16*HD; idx += 256) {
        int gi = idx >> 9, k = idx & (HD-1);
        int g = gi >> 2, ci = gi & 3;
        sWT[gi*WP + k] = Whh[(size_t)(g*512 + blk*4 + ci)*HD + k];
    }

    int rgrp = tid >> 4;
    int cc   = tid & 15;
    int r0   = rgrp*4;
    int b_u  = tid >> 2;
    int kl   = tid & 3;
    int k_u  = blk*4 + kl;

    const float* wbase = sWT + cc*WP;
    const float* h0p = sH + (size_t)(r0+0)*WP;
    const float* h1p = sH + (size_t)(r0+1)*WP;
    const float* h2p = sH + (size_t)(r0+2)*WP;
    const float* h3p = sH + (size_t)(r0+3)*WP;

    int srow0 = tid >> 7;
    int skq   = tid & 127;
    uint32_t sdst0 = (uint32_t)__cvta_generic_to_shared(sH + (size_t)srow0*WP + skq*4);
    const uint32_t SROWB = 2u*WP*4u;

    float creg = 0.f;
    __syncthreads();

    for (int t = 0; t < TDEC; ++t) {
        int n = g_nt[t];

        const float* gx = g_X + (size_t)t*BB*GG + (size_t)b_u*GG;
        float x0=0.f, x1=0.f, x2=0.f, x3=0.f;
        if (b_u < n) {
            x0 = __ldcg(gx + k_u);
            x1 = __ldcg(gx + 512 + k_u);
            x2 = __ldcg(gx + 1024 + k_u);
            x3 = __ldcg(gx + 1536 + k_u);
        }

        const float* sg0 = g_h + (size_t)(t & 1)*BB*HD + (size_t)srow0*HD + skq*4;
        for (int j = 0; srow0 + 2*j < n; ++j) {
            cpasync16(sdst0 + (uint32_t)j*SROWB, sg0 + (size_t)j*2*HD);
        }
        asm volatile("cp.async.commit_group;" ::: "memory");
        asm volatile("cp.async.wait_group 0;" ::: "memory");
        __syncthreads();

        if (r0 < n) {
            unsigned long long a00=0ull,a01=0ull,a10=0ull,a11=0ull,
                               a20=0ull,a21=0ull,a30=0ull,a31=0ull;
#pragma unroll 4
            for (int kq = 0; kq < HD/4; ++kq) {
                float4 wv = *(const float4*)(wbase + 4*kq);
                unsigned long long wxy = pack2(wv.x, wv.y);
                unsigned long long wzw = pack2(wv.z, wv.w);
                float4 v0 = *(const float4*)(h0p + 4*kq);
                float4 v1 = *(const float4*)(h1p + 4*kq);
                float4 v2 = *(const float4*)(h2p + 4*kq);
                float4 v3 = *(const float4*)(h3p + 4*kq);
                a00 = fma2(pack2(v0.x,v0.y), wxy, a00);
                a01 = fma2(pack2(v0.z,v0.w), wzw, a01);
                a10 = fma2(pack2(v1.x,v1.y), wxy, a10);
                a11 = fma2(pack2(v1.z,v1.w), wzw, a11);
                a20 = fma2(pack2(v2.x,v2.y), wxy, a20);
                a21 = fma2(pack2(v2.z,v2.w), wzw, a21);
                a30 = fma2(pack2(v3.x,v3.y), wxy, a30);
                a31 = fma2(pack2(v3.z,v3.w), wzw, a31);
            }
            sG[(r0+0)*20 + cc] = hsum2(a00) + hsum2(a01);
            sG[(r0+1)*20 + cc] = hsum2(a10) + hsum2(a11);
            sG[(r0+2)*20 + cc] = hsum2(a20) + hsum2(a21);
            sG[(r0+3)*20 + cc] = hsum2(a30) + hsum2(a31);
        }
        __syncthreads();

        if (b_u < n) {
            float zi = sG[b_u*20 +  0 + kl] + x0;
            float zf = sG[b_u*20 +  4 + kl] + x1;
            float zg = sG[b_u*20 +  8 + kl] + x2;
            float zo = sG[b_u*20 + 12 + kl] + x3;
            float ii = 1.f/(1.f+expf(-zi));
            float ff = 1.f/(1.f+expf(-zf));
            float gv = tanhf(zg);
            float oo = 1.f/(1.f+expf(-zo));
            creg = ff*creg + ii*gv;
            float hn = oo * tanhf(creg);
            g_h[(size_t)((t+1) & 1)*BB*HD + (size_t)b_u*HD + k_u] = hn;
            g_Hpk[(size_t)(g_pbase[t] + b_u)*HD + k_u] = to_tf32(hn);
        }
        gridbar((unsigned)(t+1));
    }
}

// ------------------------ kernel 5: classifier, BK=32 cp.async double-buffered tf32 mma ------------------------
__global__ void __launch_bounds__(256,2) classifier_mma(const float* __restrict__ linb,
                                                        float* __restrict__ out)
{
    int P  = g_pcount;
    int m0 = blockIdx.y * 128;
    if (m0 >= P) return;
    int v0 = blockIdx.x * 128;

    __shared__ __align__(16) float As[2][128][36];
    __shared__ __align__(16) float Bs[2][128][36];

    int tid  = threadIdx.x;
    int lane = tid & 31, wid = tid >> 5;
    int wm = wid & 1, wn = wid >> 1;
    int gq = lane >> 2, tig = lane & 3;

    // producer: 4 float4 per thread per stage for A and for B (128 rows x 8 quads)
    const float* aptr[4];
    const float* bptr[4];
    uint32_t     asm_[4];
    uint32_t     bsm_[4];
#pragma unroll
    for (int j = 0; j < 4; ++j) {
        int idx = j*256 + tid;
        int row = idx >> 3, kq = idx & 7;
        int p = m0 + row;
        aptr[j] = g_Hpk + (size_t)(p < P ? p : 0)*HD + kq*4;
        bptr[j] = g_linWr + (size_t)(v0 + row)*HD + kq*4;
        asm_[j] = (uint32_t)__cvta_generic_to_shared(&As[0][row][kq*4]);
        bsm_[j] = (uint32_t)__cvta_generic_to_shared(&Bs[0][row][kq*4]);
    }
    const uint32_t STG = 128*36*4;

    float acc[4][4][4];
#pragma unroll
    for (int i=0;i<4;i++)
#pragma unroll
        for (int j=0;j<4;j++)
#pragma unroll
            for (int q=0;q<4;q++) acc[i][j][q] = 0.f;

    // prologue: stage 0 (k = 0..31)
#pragma unroll
    for (int j = 0; j < 4; ++j) { cpasync16(asm_[j], aptr[j]); cpasync16(bsm_[j], bptr[j]); }
    asm volatile("cp.async.commit_group;" ::: "memory");

    for (int kc = 0; kc < 16; ++kc) {
        if (kc < 15) {
            uint32_t off = ((kc+1)&1) * STG;
            int kn = (kc+1)*32;
#pragma unroll
            for (int j = 0; j < 4; ++j) {
                cpasync16(asm_[j] + off, aptr[j] + kn);
                cpasync16(bsm_[j] + off, bptr[j] + kn);
            }
            asm volatile("cp.async.commit_group;" ::: "memory");
            asm volatile("cp.async.wait_group 1;" ::: "memory");
        } else {
            asm volatile("cp.async.wait_group 0;" ::: "memory");
        }
        __syncthreads();

        int buf = kc & 1;
#pragma unroll
        for (int k8 = 0; k8 < 4; ++k8) {
            int kb = k8*8;
            float af[4][4], bf[4][2];
#pragma unroll
            for (int mt=0;mt<4;mt++) {
                int rm = wm*64 + mt*16;
                af[mt][0]=As[buf][rm+gq][kb+tig];   af[mt][1]=As[buf][rm+gq+8][kb+tig];
                af[mt][2]=As[buf][rm+gq][kb+tig+4]; af[mt][3]=As[buf][rm+gq+8][kb+tig+4];
            }
#pragma unroll
            for (int nt=0;nt<4;nt++) {
                int rn = wn*32 + nt*8;
                bf[nt][0]=Bs[buf][rn+gq][kb+tig]; bf[nt][1]=Bs[buf][rn+gq][kb+tig+4];
            }
#pragma unroll
            for (int mt=0;mt<4;mt++)
#pragma unroll
                for (int nt=0;nt<4;nt++)
                    mma8(acc[mt][nt], af[mt], bf[nt]);
        }
        __syncthreads();
    }

    float2 lb[4];
#pragma unroll
    for (int nt=0;nt<4;nt++) {
        int v = v0 + wn*32 + nt*8 + tig*2;
        lb[nt] = *(const float2*)(linb + v);
    }
#pragma unroll
    for (int mt=0;mt<4;mt++) {
#pragma unroll
        for (int half=0; half<2; ++half) {
            int ml = wm*64 + mt*16 + gq + half*8;
            int p = m0 + ml;
            if (p < P) {
                int tt = g_pt[p], bb = g_pb[p];
                size_t base = ((size_t)bb*TDEC + tt)*VV + v0 + wn*32 + tig*2;
#pragma unroll
                for (int nt=0;nt<4;nt++) {
                    float2 val;
                    val.x = acc[mt][nt][half*2+0] + lb[nt].x;
                    val.y = acc[mt][nt][half*2+1] + lb[nt].y;
                    *(float2*)(out + base + nt*8) = val;
                }
            }
        }
    }
}

// ------------------------ launch ------------------------
extern "C" void kernel_launch(void* const* d_in, const int* in_sizes, int n_in,
                              void* d_out, int out_size)
{
    const float* img  = (const float*)d_in[0];
    const int*   caps = (const int*)  d_in[1];
    const int*   lens = (const int*)  d_in[2];
    const float* embW = (const float*)d_in[3];
    const float* Wih  = (const float*)d_in[4];
    const float* Whh  = (const float*)d_in[5];
    const float* bih  = (const float*)d_in[6];
    const float* bhh  = (const float*)d_in[7];
    const float* linW = (const float*)d_in[8];
    const float* linb = (const float*)d_in[9];
    float* out = (float*)d_out;

    static cudaStream_t s2;
    static cudaEvent_t evA, evB;
    static int inited = 0;
    if (!inited) {
        cudaFuncSetAttribute(recur_kernel,
                             cudaFuncAttributeMaxDynamicSharedMemorySize, RECUR_SMEM);
        cudaStreamCreateWithFlags(&s2, cudaStreamNonBlocking);
        cudaEventCreateWithFlags(&evA, cudaEventDisableTiming);
        cudaEventCreateWithFlags(&evB, cudaEventDisableTiming);
        inited = 1;
    }

    setup_kernel<<<1, 256>>>(img, caps, lens, out, out_size);

    // fork: round_linW + zerofill on s2, concurrent with xgate + recur
    cudaEventRecord(evA, 0);
    cudaStreamWaitEvent(s2, evA, 0);
    round_linW<<<(VV*HD/4)/256, 256, 0, s2>>>(linW);
    zerofill_kernel<<<BB*TDEC, 256, 0, s2>>>(out);
    cudaEventRecord(evB, s2);

    xgate_mma<<<dim3(GG/128, (MAXP+127)/128), 256>>>(embW, Wih, bih, bhh);
    recur_kernel<<<NBLK, 256, RECUR_SMEM>>>(Whh);

    cudaStreamWaitEvent(0, evB, 0);
    classifier_mma<<<dim3(VV/128, (MAXP+127)/128), 256>>>(linb, out);
}